// round 6
// baseline (speedup 1.0000x reference)
#include <cuda_runtime.h>
#include <cstdint>
#include <cstddef>

// ---------------------------------------------------------------- problem
#define B_DIM   32
#define IN_DIM  4096
#define OUT_DIM 14336

// ---------------------------------------------------------------- tiling
#define M_TILE   128          // o-rows per CTA (8 warps x m16)
#define NTHREADS 256
#define SC_K     512          // x superchunk staged in smem
#define NSC      (IN_DIM / SC_K)   // 8
#define CH_K     64           // W chunk (== absmax blocksize)
#define NCH      (SC_K / CH_K)     // 8
#define NCHTOT   (IN_DIM / CH_K)   // 64
#define XS_STRIDE 40          // floats per k-row of xs (32 + 8 pad; 40%32==8)
#define SMEM_BYTES (SC_K * XS_STRIDE * 4)   // 81920

__constant__ float c_nf4[16] = {
    -1.0f, -0.6961928009986877f, -0.5250730514526367f, -0.39491748809814453f,
    -0.28444138169288635f, -0.18477343022823334f, -0.09105003625154495f, 0.0f,
    0.07958029955625534f, 0.16093020141124725f, 0.24611230194568634f,
    0.33791524171829224f, 0.44070982933044434f, 0.5626170039176941f,
    0.7229568362236023f, 1.0f};

// round-to-nearest tf32 (zero-mean rounding error; truncation would bias ~1e-3)
__device__ __forceinline__ float to_tf32(float f) {
    float r;
    asm("cvt.rna.tf32.f32 %0, %1;" : "=f"(r) : "f"(f));
    return r;
}

// m16n8k8 tf32 mma (baseline PTX, sm_80+; no 'a' target needed)
#define MMA4(d, a0, a1, a2, a3, b0, b1)                                   \
    asm volatile(                                                         \
        "mma.sync.aligned.m16n8k8.row.col.f32.tf32.tf32.f32 "             \
        "{%0,%1,%2,%3}, {%4,%5,%6,%7}, {%8,%9}, {%0,%1,%2,%3};"           \
        : "+f"((d)[0]), "+f"((d)[1]), "+f"((d)[2]), "+f"((d)[3])          \
        : "r"(a0), "r"(a1), "r"(a2), "r"(a3),                             \
          "r"(__float_as_uint(b0)), "r"(__float_as_uint(b1)))

// ---------------------------------------------------------------- kernel
// Warp w owns o-rows [o0+16w, +16), all 32 batch cols (4 n8-tiles).
// Lane (gid = lid>>2, c = lid&3).
//  A frag (W): a0=(gid,c) a1=(gid+8,c) a2=(gid,c+4) a3=(gid+8,c+4)
//  B frag (x): b0=(k=c, n=gid+8*bt) b1=(k=c+4, n)
//  D: d0=(gid,2c) d1=(gid,2c+1) d2=(gid+8,2c) d3=(gid+8,2c+1)
__global__ __launch_bounds__(NTHREADS, 1)
void nf4_mma16n8(const float* __restrict__ x,
                 const int*   __restrict__ codes,
                 const float* __restrict__ absmax,
                 const float* __restrict__ bias,
                 float*       __restrict__ out)
{
    extern __shared__ float xs[];   // [SC_K][XS_STRIDE], btile-interleaved cols

    const int tid = threadIdx.x;
    const int w   = tid >> 5;
    const int lid = tid & 31;
    const int gid = lid >> 2;       // 0..7
    const int c   = lid & 3;        // 0..3
    const int o0  = blockIdx.x * M_TILE;

    const float nf4v = c_nf4[lid & 15];   // codebook in registers, shfl lookup

    // -------- staging identity: lane holds words for row (lid&15), t-half lid>>4
    const int srow  = lid & 15;
    const int thalf = lid >> 4;
    const size_t row_g = (size_t)(o0 + 16 * w + srow);
    const int*   cbase = codes  + row_g * IN_DIM + thalf * 32;
    const float* abase = absmax + row_g * (IN_DIM / 64);

    float acc[4][4];                 // [btile][d0..d3]
#pragma unroll
    for (int i = 0; i < 4; ++i)
#pragma unroll
        for (int j = 0; j < 4; ++j) acc[i][j] = 0.0f;

    // raw code prefetch buffer: 8 int4 = 32 codes (one CH_K chunk per lane)
    int4 raw[8];
#pragma unroll
    for (int j = 0; j < 4; ++j) {
        raw[2 * j]     = *reinterpret_cast<const int4*>(cbase + j * 8);
        raw[2 * j + 1] = *reinterpret_cast<const int4*>(cbase + j * 8 + 4);
    }
    float am_s = __ldg(abase);       // absmax block for chunk 0
    uint32_t pk[4];
    int gch = 0;                     // global chunk id

    // x staging identity: lane b = lid, permuted col, row kq = 8p + w
    const int bb = lid;
    const int pb = ((bb & 7) << 2) | (bb >> 3);
    const float* xrow = x + (size_t)bb * IN_DIM;

    for (int sc = 0; sc < NSC; ++sc) {
        __syncthreads();             // prior superchunk's xs reads done
        // -------- stage x superchunk: conflict-free STS (pb distinct/warp)
#pragma unroll
        for (int p = 0; p < 16; ++p) {
            const int kq = p * 8 + w;                  // float4 row 0..127
            const float4 v = *reinterpret_cast<const float4*>(
                xrow + sc * SC_K + kq * 4);
            xs[(kq * 4 + 0) * XS_STRIDE + pb] = to_tf32(v.x);
            xs[(kq * 4 + 1) * XS_STRIDE + pb] = to_tf32(v.y);
            xs[(kq * 4 + 2) * XS_STRIDE + pb] = to_tf32(v.z);
            xs[(kq * 4 + 3) * XS_STRIDE + pb] = to_tf32(v.w);
        }
        __syncthreads();

        for (int cc = 0; cc < NCH; ++cc) {
            // -------- pack current chunk: 8 codes -> 1 nibble word
#pragma unroll
            for (int j = 0; j < 4; ++j) {
                const int4 r0 = raw[2 * j], r1 = raw[2 * j + 1];
                pk[j] = (uint32_t)(r0.x & 15)        | ((uint32_t)(r0.y & 15) << 4)
                      | ((uint32_t)(r0.z & 15) << 8) | ((uint32_t)(r0.w & 15) << 12)
                      | ((uint32_t)(r1.x & 15) << 16)| ((uint32_t)(r1.y & 15) << 20)
                      | ((uint32_t)(r1.z & 15) << 24)| ((uint32_t)(r1.w & 15) << 28);
            }
            const float am_cur = am_s;

            // -------- prefetch next chunk's codes + absmax
            ++gch;
            if (gch < NCHTOT) {
#pragma unroll
                for (int j = 0; j < 4; ++j) {
                    raw[2 * j]     = *reinterpret_cast<const int4*>(
                        cbase + gch * CH_K + j * 8);
                    raw[2 * j + 1] = *reinterpret_cast<const int4*>(
                        cbase + gch * CH_K + j * 8 + 4);
                }
                am_s = __ldg(abase + gch);
            }

            const float am_lo = __shfl_sync(0xffffffffu, am_cur, gid);
            const float am_hi = __shfl_sync(0xffffffffu, am_cur, gid + 8);
            const float* xk = xs + (cc * CH_K) * XS_STRIDE;

            // -------- 8 k-steps of m16n8k8
#pragma unroll
            for (int t = 0; t < 8; ++t) {
                const uint32_t wlo =
                    __shfl_sync(0xffffffffu, pk[t & 3], gid + ((t >> 2) << 4));
                const uint32_t whi =
                    __shfl_sync(0xffffffffu, pk[t & 3], gid + 8 + ((t >> 2) << 4));
                const uint32_t a0 = __float_as_uint(to_tf32(
                    __shfl_sync(0xffffffffu, nf4v, (wlo >> (4 * c)) & 15) * am_lo));
                const uint32_t a2 = __float_as_uint(to_tf32(
                    __shfl_sync(0xffffffffu, nf4v, (wlo >> (4 * c + 16)) & 15) * am_lo));
                const uint32_t a1 = __float_as_uint(to_tf32(
                    __shfl_sync(0xffffffffu, nf4v, (whi >> (4 * c)) & 15) * am_hi));
                const uint32_t a3 = __float_as_uint(to_tf32(
                    __shfl_sync(0xffffffffu, nf4v, (whi >> (4 * c + 16)) & 15) * am_hi));

                // one LDS.128 = b0 (or b1) for all 4 btiles; conflict-free
                const float4 b0v = *reinterpret_cast<const float4*>(
                    xk + (t * 8 + c) * XS_STRIDE + gid * 4);
                const float4 b1v = *reinterpret_cast<const float4*>(
                    xk + (t * 8 + c + 4) * XS_STRIDE + gid * 4);

                MMA4(acc[0], a0, a1, a2, a3, b0v.x, b1v.x);
                MMA4(acc[1], a0, a1, a2, a3, b0v.y, b1v.y);
                MMA4(acc[2], a0, a1, a2, a3, b0v.z, b1v.z);
                MMA4(acc[3], a0, a1, a2, a3, b0v.w, b1v.w);
            }
        }
    }

    // -------- epilogue: bias + scattered stores (all 32x128 per CTA covered)
    const int o_lo = o0 + 16 * w + gid;
    const int o_hi = o_lo + 8;
    const float bl = __ldg(bias + o_lo);
    const float bh = __ldg(bias + o_hi);
#pragma unroll
    for (int bt = 0; bt < 4; ++bt) {
        const int b0 = bt * 8 + 2 * c;
        const int b1 = b0 + 1;
        out[(size_t)b0 * OUT_DIM + o_lo] = acc[bt][0] + bl;
        out[(size_t)b1 * OUT_DIM + o_lo] = acc[bt][1] + bl;
        out[(size_t)b0 * OUT_DIM + o_hi] = acc[bt][2] + bh;
        out[(size_t)b1 * OUT_DIM + o_hi] = acc[bt][3] + bh;
    }
}

// ---------------------------------------------------------------- launch
// Inputs (metadata order): x f32[32,4096], codes i32[14336,4096],
//                          absmax f32[917504], bias f32[14336]
// Output: f32[32,14336]
extern "C" void kernel_launch(void* const* d_in, const int* in_sizes, int n_in,
                              void* d_out, int out_size)
{
    const float* x      = (const float*)d_in[0];
    const int*   codes  = (const int*)  d_in[1];
    const float* absmax = (const float*)d_in[2];
    const float* bias   = (const float*)d_in[3];
    float*       out    = (float*)d_out;

    cudaFuncSetAttribute(nf4_mma16n8,
                         cudaFuncAttributeMaxDynamicSharedMemorySize, SMEM_BYTES);
    nf4_mma16n8<<<OUT_DIM / M_TILE, NTHREADS, SMEM_BYTES>>>(
        x, codes, absmax, bias, out);
}

// round 9
// speedup vs baseline: 1.5440x; 1.5440x over previous
#include <cuda_runtime.h>
#include <cuda_fp16.h>
#include <cstdint>
#include <cstddef>

// ---------------------------------------------------------------- problem
#define B_DIM   32
#define IN_DIM  4096
#define OUT_DIM 14336

// ---------------------------------------------------------------- tiling
#define KSPLIT   4
#define K_RANGE  (IN_DIM / KSPLIT)    // 1024 k per CTA
#define CH_K     64                   // chunk (== absmax blocksize)
#define NCH      (K_RANGE / CH_K)     // 16
#define M_TILE   128                  // 8 warps x 16 o-rows
#define NTHREADS 256
#define XS_S     40                   // u32 per k2-row (160B; addr16 ≡ 2 mod 8)
#define XS_ROWS  (K_RANGE / 2)        // 512 fp16x2 rows
#define SMEM_BYTES (XS_ROWS * XS_S * 4)   // 81920

// split-K partials [KSPLIT][B][OUT] fp32 = 7.34 MB (static, no alloc)
__device__ float g_part[(size_t)KSPLIT * B_DIM * OUT_DIM];

__constant__ float c_nf4[16] = {
    -1.0f, -0.6961928009986877f, -0.5250730514526367f, -0.39491748809814453f,
    -0.28444138169288635f, -0.18477343022823334f, -0.09105003625154495f, 0.0f,
    0.07958029955625534f, 0.16093020141124725f, 0.24611230194568634f,
    0.33791524171829224f, 0.44070982933044434f, 0.5626170039176941f,
    0.7229568362236023f, 1.0f};

// pack two f32 -> f16x2 (lo = first arg). PTX: first source -> upper half.
__device__ __forceinline__ uint32_t f16x2_pack(float lo, float hi) {
    uint32_t r;
    asm("cvt.rn.f16x2.f32 %0, %1, %2;" : "=r"(r) : "f"(hi), "f"(lo));
    return r;
}

// m16n8k16 f16 mma, fp32 accum (baseline PTX, sm_80+)
#define MMAH(d, a0, a1, a2, a3, b0, b1)                                   \
    asm volatile(                                                         \
        "mma.sync.aligned.m16n8k16.row.col.f32.f16.f16.f32 "              \
        "{%0,%1,%2,%3}, {%4,%5,%6,%7}, {%8,%9}, {%0,%1,%2,%3};"           \
        : "+f"((d)[0]), "+f"((d)[1]), "+f"((d)[2]), "+f"((d)[3])          \
        : "r"(a0), "r"(a1), "r"(a2), "r"(a3), "r"(b0), "r"(b1))

// ---------------------------------------------------------------- gemm
// Warp w owns o-rows [o0+16w, +16). Lane (gid=lid>>2, c=lid&3).
// A frag (W, k16): a0={(gid,2c),(gid,2c+1)} a1={(gid+8,..)} a2={(gid,2c+8..9)}
// B frag (x):      b0={(2c,n),(2c+1,n)}     b1={(2c+8,n),(2c+9,n)}
// D:               d0=(gid,2c) d1=(gid,2c+1) d2=(gid+8,2c) d3=(gid+8,2c+1)
__global__ __launch_bounds__(NTHREADS)
void nf4_f16_mma(const float* __restrict__ x,
                 const int*   __restrict__ codes,
                 const float* __restrict__ absmax)
{
    extern __shared__ uint32_t xs[];   // [XS_ROWS][XS_S] fp16x2, permuted cols

    const int tid = threadIdx.x;
    const int w   = tid >> 5;
    const int lid = tid & 31;
    const int gid = lid >> 2;
    const int c   = lid & 3;
    const int o0  = blockIdx.x * M_TILE;
    const int kz  = blockIdx.y;

    const float nf4v = c_nf4[lid & 15];   // codebook in regs, shfl lookup

    // -------- stage x once: [32 b][1024 k] fp32 -> xs[k2][perm(b)] fp16x2
    {
        const int b  = tid >> 3;          // 0..31
        const int t8 = tid & 7;
        const int pb = ((b & 7) << 2) | (b >> 3);
        const float* xr = x + (size_t)b * IN_DIM + kz * K_RANGE;
#pragma unroll
        for (int j = 0; j < 32; ++j) {
            const float4 v = *reinterpret_cast<const float4*>(xr + j * 32 + t8 * 4);
            const int k2 = j * 16 + t8 * 2;
            xs[(k2 + 0) * XS_S + pb] = f16x2_pack(v.x, v.y);
            xs[(k2 + 1) * XS_S + pb] = f16x2_pack(v.z, v.w);
        }
    }
    __syncthreads();   // only sync in the kernel; warps free-run after this

    // -------- code-holder identity: lane holds row (lid&15), k-half (lid>>4)
    const int srow  = lid & 15;
    const int thalf = lid >> 4;
    const size_t rowg = (size_t)(o0 + 16 * w + srow);
    const int*   cb = codes  + rowg * IN_DIM + kz * K_RANGE + thalf * 32;
    const float* ab = absmax + rowg * (IN_DIM / 64) + kz * (K_RANGE / 64);

    float acc[4][4];
#pragma unroll
    for (int i = 0; i < 4; ++i)
#pragma unroll
        for (int j = 0; j < 4; ++j) acc[i][j] = 0.0f;

    // prefetch chunk 0 codes (lane's 32 codes = 8 int4) + absmax
    int4 raw[8];
#pragma unroll
    for (int j = 0; j < 4; ++j) {
        raw[2 * j]     = *reinterpret_cast<const int4*>(cb + j * 8);
        raw[2 * j + 1] = *reinterpret_cast<const int4*>(cb + j * 8 + 4);
    }
    float am_s = __ldg(ab);

    for (int ch = 0; ch < NCH; ++ch) {
        // pack 32 codes -> 4 nibble words (nibble i of pk[j] = k off j*8+i)
        uint32_t pk[4];
#pragma unroll
        for (int j = 0; j < 4; ++j) {
            const int4 r0 = raw[2 * j], r1 = raw[2 * j + 1];
            pk[j] = (uint32_t)(r0.x & 15)        | ((uint32_t)(r0.y & 15) << 4)
                  | ((uint32_t)(r0.z & 15) << 8) | ((uint32_t)(r0.w & 15) << 12)
                  | ((uint32_t)(r1.x & 15) << 16)| ((uint32_t)(r1.y & 15) << 20)
                  | ((uint32_t)(r1.z & 15) << 24)| ((uint32_t)(r1.w & 15) << 28);
        }
        const float am_cur = am_s;

        // prefetch next chunk
        if (ch + 1 < NCH) {
            const int* cn = cb + (ch + 1) * CH_K;
#pragma unroll
            for (int j = 0; j < 4; ++j) {
                raw[2 * j]     = *reinterpret_cast<const int4*>(cn + j * 8);
                raw[2 * j + 1] = *reinterpret_cast<const int4*>(cn + j * 8 + 4);
            }
            am_s = __ldg(ab + ch + 1);
        }

        const float am_lo = __shfl_sync(0xffffffffu, am_cur, gid);
        const float am_hi = __shfl_sync(0xffffffffu, am_cur, gid + 8);
        const uint32_t* xrow = xs + (ch * 32) * XS_S;   // 32 k2-rows per chunk

        // -------- 4 k16-steps
#pragma unroll
        for (int t = 0; t < 4; ++t) {
            const int j0 = (2 * t) & 3;
            const int sl = gid + ((t >> 1) << 4);   // holder lane, row gid
            const uint32_t wl0 = __shfl_sync(0xffffffffu, pk[j0],     sl);
            const uint32_t wl1 = __shfl_sync(0xffffffffu, pk[j0 + 1], sl);
            const uint32_t wh0 = __shfl_sync(0xffffffffu, pk[j0],     sl + 8);
            const uint32_t wh1 = __shfl_sync(0xffffffffu, pk[j0 + 1], sl + 8);
            const int sh = 8 * c;

            const uint32_t a0 = f16x2_pack(
                __shfl_sync(0xffffffffu, nf4v, (wl0 >> sh) & 15) * am_lo,
                __shfl_sync(0xffffffffu, nf4v, (wl0 >> (sh + 4)) & 15) * am_lo);
            const uint32_t a1 = f16x2_pack(
                __shfl_sync(0xffffffffu, nf4v, (wh0 >> sh) & 15) * am_hi,
                __shfl_sync(0xffffffffu, nf4v, (wh0 >> (sh + 4)) & 15) * am_hi);
            const uint32_t a2 = f16x2_pack(
                __shfl_sync(0xffffffffu, nf4v, (wl1 >> sh) & 15) * am_lo,
                __shfl_sync(0xffffffffu, nf4v, (wl1 >> (sh + 4)) & 15) * am_lo);
            const uint32_t a3 = f16x2_pack(
                __shfl_sync(0xffffffffu, nf4v, (wh1 >> sh) & 15) * am_hi,
                __shfl_sync(0xffffffffu, nf4v, (wh1 >> (sh + 4)) & 15) * am_hi);

            // one LDS.128 = b0 (resp. b1) for all 4 btiles; phase-conflict-free
            const uint4 b0 = *reinterpret_cast<const uint4*>(
                xrow + (8 * t + c) * XS_S + gid * 4);
            const uint4 b1 = *reinterpret_cast<const uint4*>(
                xrow + (8 * t + c + 4) * XS_S + gid * 4);

            MMAH(acc[0], a0, a1, a2, a3, b0.x, b1.x);
            MMAH(acc[1], a0, a1, a2, a3, b0.y, b1.y);
            MMAH(acc[2], a0, a1, a2, a3, b0.z, b1.z);
            MMAH(acc[3], a0, a1, a2, a3, b0.w, b1.w);
        }
    }

    // -------- epilogue: partials to g_part[kz][b][o]
    const int o_lo = o0 + 16 * w + gid;
    const int o_hi = o_lo + 8;
    float* gp = g_part + (size_t)kz * B_DIM * OUT_DIM;
#pragma unroll
    for (int bt = 0; bt < 4; ++bt) {
        const int b0i = bt * 8 + 2 * c;
        gp[(size_t)(b0i    ) * OUT_DIM + o_lo] = acc[bt][0];
        gp[(size_t)(b0i + 1) * OUT_DIM + o_lo] = acc[bt][1];
        gp[(size_t)(b0i    ) * OUT_DIM + o_hi] = acc[bt][2];
        gp[(size_t)(b0i + 1) * OUT_DIM + o_hi] = acc[bt][3];
    }
}

// ---------------------------------------------------------------- reduce
__global__ __launch_bounds__(256)
void nf4_reduce(const float* __restrict__ bias, float* __restrict__ out)
{
    const int idx = blockIdx.x * blockDim.x + threadIdx.x;  // float4 index
    const int o4  = idx % (OUT_DIM / 4);
    const int b   = idx / (OUT_DIM / 4);
    float4 s = reinterpret_cast<const float4*>(bias)[o4];
    const float* p = g_part + (size_t)b * OUT_DIM + (size_t)o4 * 4;
#pragma unroll
    for (int z = 0; z < KSPLIT; ++z) {
        const float4 v = *reinterpret_cast<const float4*>(
            p + (size_t)z * B_DIM * OUT_DIM);
        s.x += v.x; s.y += v.y; s.z += v.z; s.w += v.w;
    }
    reinterpret_cast<float4*>(out)[(size_t)b * (OUT_DIM / 4) + o4] = s;
}

// ---------------------------------------------------------------- launch
// Inputs (metadata order): x f32[32,4096], codes i32[14336,4096],
//                          absmax f32[917504], bias f32[14336]
// Output: f32[32,14336]
extern "C" void kernel_launch(void* const* d_in, const int* in_sizes, int n_in,
                              void* d_out, int out_size)
{
    const float* x      = (const float*)d_in[0];
    const int*   codes  = (const int*)  d_in[1];
    const float* absmax = (const float*)d_in[2];
    const float* bias   = (const float*)d_in[3];
    float*       out    = (float*)d_out;

    cudaFuncSetAttribute(nf4_f16_mma,
                         cudaFuncAttributeMaxDynamicSharedMemorySize, SMEM_BYTES);
    dim3 grid(OUT_DIM / M_TILE, KSPLIT);          // (112, 4) = 448 CTAs
    nf4_f16_mma<<<grid, NTHREADS, SMEM_BYTES>>>(x, codes, absmax);

    const int n4 = B_DIM * OUT_DIM / 4;           // 114688
    nf4_reduce<<<n4 / 256, 256>>>(bias, out);     // 448 blocks, exact
}